// round 1
// baseline (speedup 1.0000x reference)
#include <cuda_runtime.h>
#include <math_constants.h>

// ---------------------------------------------------------------------------
// ListNet loss: segmented (per-week) softmax cross-entropy over sorted segments
//   BATCH = 4,194,304 items, NUM_WEEKS = 262,144 segments (mean length 16)
// ---------------------------------------------------------------------------

#define NW               262144
#define WARPS_PER_BLOCK  8
#define GRID2            (NW / WARPS_PER_BLOCK)   // 32768 blocks in week kernel
#define EPSV             1e-8f

// Scratch: __device__ globals (no allocation allowed).
// Zero-initialized at module load; boundary entries are rewritten with the
// SAME values on every call (inputs fixed), empty weeks stay lo=hi=0 -> n=0.
__device__ int   g_lo[NW];
__device__ int   g_hi[NW];
__device__ float g_part_tot[GRID2];
__device__ float g_part_cnt[GRID2];

// ---------------------------------------------------------------------------
// K1: detect segment boundaries in the sorted week_indices array.
// ---------------------------------------------------------------------------
__global__ void boundaries_kernel(const int* __restrict__ idx, int n) {
    int i = blockIdx.x * blockDim.x + threadIdx.x;
    if (i >= n) return;
    int w = idx[i];
    if (i == 0 || idx[i - 1] != w) g_lo[w] = i;
    if (i == n - 1 || idx[i + 1] != w) g_hi[w] = i + 1;
}

// ---------------------------------------------------------------------------
// K2: one warp per week. Compute per-week softmax CE contribution.
//   item_sum = sum_i p_true_i * log(p_pred_i + eps)
//   valid    = (count >= 2)
// Block-reduce 8 weeks -> per-block partials.
// ---------------------------------------------------------------------------
__global__ __launch_bounds__(WARPS_PER_BLOCK * 32)
void week_kernel(const float* __restrict__ scores,
                 const float* __restrict__ labels) {
    const int warp = threadIdx.x >> 5;
    const int lane = threadIdx.x & 31;
    const int w    = blockIdx.x * WARPS_PER_BLOCK + warp;

    float item_sum = 0.0f;
    float valid    = 0.0f;

    const int lo = g_lo[w];
    const int hi = g_hi[w];
    const int n  = hi - lo;

    if (n >= 2) {
        valid = 1.0f;
        float mL = -CUDART_INF_F, mS = -CUDART_INF_F;

        if (n <= 128) {
            // Register-resident path (covers all realistic segment lengths;
            // max expected ~48 for binomial(4M, 1/262144)).
            float lab[4], sc[4];
#pragma unroll
            for (int k = 0; k < 4; k++) {
                int i = lo + lane + (k << 5);
                bool v = (i < hi);
                lab[k] = v ? labels[i] : -1e30f;   // exp() underflows to 0
                sc[k]  = v ? scores[i] : -1e30f;
                mL = fmaxf(mL, lab[k]);
                mS = fmaxf(mS, sc[k]);
            }
#pragma unroll
            for (int o = 16; o; o >>= 1) {
                mL = fmaxf(mL, __shfl_xor_sync(0xffffffffu, mL, o));
                mS = fmaxf(mS, __shfl_xor_sync(0xffffffffu, mS, o));
            }

            float eL[4], eS[4];
            float sL = 0.0f, sS = 0.0f;
#pragma unroll
            for (int k = 0; k < 4; k++) {
                eL[k] = __expf(lab[k] - mL);       // 0 for padded lanes
                eS[k] = __expf(sc[k]  - mS);
                sL += eL[k];
                sS += eS[k];
            }
#pragma unroll
            for (int o = 16; o; o >>= 1) {
                sL += __shfl_xor_sync(0xffffffffu, sL, o);
                sS += __shfl_xor_sync(0xffffffffu, sS, o);
            }

            const float invL = 1.0f / sL;
            const float invS = 1.0f / sS;
#pragma unroll
            for (int k = 0; k < 4; k++) {
                // padded lanes: eL == 0 exactly -> contribution exactly 0
                item_sum += (eL[k] * invL) * __logf(eS[k] * invS + EPSV);
            }
        } else {
            // Fallback: strided re-read (L2-resident). Practically never taken.
            for (int i = lo + lane; i < hi; i += 32) {
                mL = fmaxf(mL, labels[i]);
                mS = fmaxf(mS, scores[i]);
            }
#pragma unroll
            for (int o = 16; o; o >>= 1) {
                mL = fmaxf(mL, __shfl_xor_sync(0xffffffffu, mL, o));
                mS = fmaxf(mS, __shfl_xor_sync(0xffffffffu, mS, o));
            }
            float sL = 0.0f, sS = 0.0f;
            for (int i = lo + lane; i < hi; i += 32) {
                sL += __expf(labels[i] - mL);
                sS += __expf(scores[i] - mS);
            }
#pragma unroll
            for (int o = 16; o; o >>= 1) {
                sL += __shfl_xor_sync(0xffffffffu, sL, o);
                sS += __shfl_xor_sync(0xffffffffu, sS, o);
            }
            const float invL = 1.0f / sL;
            const float invS = 1.0f / sS;
            for (int i = lo + lane; i < hi; i += 32) {
                float pt = __expf(labels[i] - mL) * invL;
                float pp = __expf(scores[i] - mS) * invS;
                item_sum += pt * __logf(pp + EPSV);
            }
        }

        // reduce item_sum across the warp
#pragma unroll
        for (int o = 16; o; o >>= 1)
            item_sum += __shfl_xor_sync(0xffffffffu, item_sum, o);
    }

    // Block-level accumulation of the 8 weeks handled by this block.
    __shared__ float s_t[WARPS_PER_BLOCK];
    __shared__ float s_c[WARPS_PER_BLOCK];
    if (lane == 0) {
        s_t[warp] = item_sum;
        s_c[warp] = valid;
    }
    __syncthreads();
    if (threadIdx.x == 0) {
        float t = 0.0f, c = 0.0f;
#pragma unroll
        for (int k = 0; k < WARPS_PER_BLOCK; k++) { t += s_t[k]; c += s_c[k]; }
        g_part_tot[blockIdx.x] = t;
        g_part_cnt[blockIdx.x] = c;
    }
}

// ---------------------------------------------------------------------------
// K3: single-block final reduction over 32768 partials.
// ---------------------------------------------------------------------------
__global__ __launch_bounds__(1024)
void finalize_kernel(float* __restrict__ out) {
    float t = 0.0f, c = 0.0f;
    for (int i = threadIdx.x; i < GRID2; i += 1024) {
        t += g_part_tot[i];
        c += g_part_cnt[i];
    }
#pragma unroll
    for (int o = 16; o; o >>= 1) {
        t += __shfl_xor_sync(0xffffffffu, t, o);
        c += __shfl_xor_sync(0xffffffffu, c, o);
    }
    __shared__ float sh_t[32];
    __shared__ float sh_c[32];
    const int warp = threadIdx.x >> 5;
    const int lane = threadIdx.x & 31;
    if (lane == 0) { sh_t[warp] = t; sh_c[warp] = c; }
    __syncthreads();
    if (warp == 0) {
        t = sh_t[lane];
        c = sh_c[lane];
#pragma unroll
        for (int o = 16; o; o >>= 1) {
            t += __shfl_xor_sync(0xffffffffu, t, o);
            c += __shfl_xor_sync(0xffffffffu, c, o);
        }
        if (lane == 0) {
            out[0] = (c > 0.0f) ? (-t / fmaxf(c, 1.0f)) : 0.0f;
        }
    }
}

// ---------------------------------------------------------------------------
// Launch: inputs per metadata order: scores(f32), labels(f32),
//         week_indices(i32), num_weeks(i32 scalar, ignored — compile-time).
// ---------------------------------------------------------------------------
extern "C" void kernel_launch(void* const* d_in, const int* in_sizes, int n_in,
                              void* d_out, int out_size) {
    const float* scores = (const float*)d_in[0];
    const float* labels = (const float*)d_in[1];
    const int*   idx    = (const int*)d_in[2];
    const int n = in_sizes[0];

    boundaries_kernel<<<(n + 255) / 256, 256>>>(idx, n);
    week_kernel<<<GRID2, WARPS_PER_BLOCK * 32>>>(scores, labels);
    finalize_kernel<<<1, 1024>>>((float*)d_out);
}

// round 2
// speedup vs baseline: 2.0091x; 2.0091x over previous
#include <cuda_runtime.h>

// ---------------------------------------------------------------------------
// ListNet loss: per-week softmax cross-entropy over sorted segments.
// BATCH = 4,194,304 items, NUM_WEEKS = 262,144 (mean segment length 16).
// Single fused main kernel: binary-search week boundaries, stage items in
// smem, 4-lane groups per week, register-stashed exp for n<=32.
// ---------------------------------------------------------------------------

#define NW        262144
#define WPB       64                // weeks per block
#define THREADS   256               // 64 groups of 4 lanes
#define GRID1     (NW / WPB)        // 4096 blocks
#define CAP       2048              // smem item capacity (mean 1024, ~6 sigma = 1200)
#define EPSV      1e-8f
#define NEG_BIG   -1e30f

__device__ float g_part_tot[GRID1];
__device__ float g_part_cnt[GRID1];

__device__ __forceinline__ int lower_bound_dev(const int* __restrict__ a,
                                               int n, int key) {
    int lo = 0, hi = n;
    while (lo < hi) {
        int mid = (lo + hi) >> 1;
        if (__ldg(a + mid) < key) lo = mid + 1; else hi = mid;
    }
    return lo;
}

// mask covering this thread's 4-lane group (legal under group-uniform branches)
__device__ __forceinline__ unsigned gmask() {
    return 0xFu << (((threadIdx.x & 31) >> 2) << 2);
}

__device__ __forceinline__ float gmax(float v, unsigned m) {
    v = fmaxf(v, __shfl_xor_sync(m, v, 1, 4));
    v = fmaxf(v, __shfl_xor_sync(m, v, 2, 4));
    return v;
}
__device__ __forceinline__ float gsum(float v, unsigned m) {
    v += __shfl_xor_sync(m, v, 1, 4);
    v += __shfl_xor_sync(m, v, 2, 4);
    return v;
}

__global__ __launch_bounds__(THREADS)
void listnet_kernel(const float* __restrict__ scores,
                    const float* __restrict__ labels,
                    const int*   __restrict__ idx, int n)
{
    __shared__ float s_sc[CAP];
    __shared__ float s_lab[CAP];
    __shared__ int   s_lb[WPB + 1];
    __shared__ float s_wt[THREADS / 32];
    __shared__ float s_wc[THREADS / 32];

    const int tid = threadIdx.x;
    const int W0  = blockIdx.x * WPB;

    // 1. per-week segment starts via binary search (L2-resident idx)
    if (tid <= WPB) s_lb[tid] = lower_bound_dev(idx, n, W0 + tid);
    __syncthreads();

    const int start  = s_lb[0];
    const int end    = s_lb[WPB];
    const int count  = end - start;
    const bool smemok = (count <= CAP);   // block-uniform

    // 2. stage this block's contiguous item range into smem (coalesced)
    if (smemok) {
        for (int i = tid; i < count; i += THREADS) {
            s_sc[i]  = scores[start + i];
            s_lab[i] = labels[start + i];
        }
    }
    __syncthreads();

    // 3. group (4 lanes) per week
    const unsigned gm = gmask();
    const int g    = tid >> 2;          // 0..63
    const int sub  = tid & 3;
    const int a    = s_lb[g]     - start;
    const int b    = s_lb[g + 1] - start;
    const int nseg = b - a;

    float item_sum = 0.0f;

    if (smemok) {
        // common fast path: register-stashed (correct for nseg <= 32;
        // longer segments are overwritten by the general path below)
        float lab[8], sc[8];
        float mL = NEG_BIG, mS = NEG_BIG;
#pragma unroll
        for (int k = 0; k < 8; k++) {
            int  j  = a + sub + (k << 2);
            bool v  = (j < b);
            int  jj = v ? j : 0;
            float l = s_lab[jj], s = s_sc[jj];
            lab[k] = v ? l : NEG_BIG;
            sc[k]  = v ? s : NEG_BIG;
            mL = fmaxf(mL, lab[k]);
            mS = fmaxf(mS, sc[k]);
        }
        mL = gmax(mL, gm);
        mS = gmax(mS, gm);

        float sL = 0.0f, sS = 0.0f;
#pragma unroll
        for (int k = 0; k < 8; k++) {
            lab[k] = __expf(lab[k] - mL);   // exactly 0 for padded slots
            sc[k]  = __expf(sc[k]  - mS);
            sL += lab[k];
            sS += sc[k];
        }
        sL = gsum(sL, gm);
        sS = gsum(sS, gm);

        const float invL = 1.0f / sL;
        const float invS = 1.0f / sS;
#pragma unroll
        for (int k = 0; k < 8; k++)
            item_sum += (lab[k] * invL) * __logf(sc[k] * invS + EPSV);
    }

    if (!smemok || nseg > 32) {
        // rare general path: strided 3-pass (smem if staged, else global/L2)
        float mL = NEG_BIG, mS = NEG_BIG;
        for (int j = a + sub; j < b; j += 4) {
            float l = smemok ? s_lab[j] : __ldg(labels + start + j);
            float s = smemok ? s_sc[j]  : __ldg(scores + start + j);
            mL = fmaxf(mL, l);
            mS = fmaxf(mS, s);
        }
        mL = gmax(mL, gm);
        mS = gmax(mS, gm);

        float sL = 0.0f, sS = 0.0f;
        for (int j = a + sub; j < b; j += 4) {
            float l = smemok ? s_lab[j] : __ldg(labels + start + j);
            float s = smemok ? s_sc[j]  : __ldg(scores + start + j);
            sL += __expf(l - mL);
            sS += __expf(s - mS);
        }
        sL = gsum(sL, gm);
        sS = gsum(sS, gm);

        const float invL = 1.0f / sL;
        const float invS = 1.0f / sS;
        item_sum = 0.0f;
        for (int j = a + sub; j < b; j += 4) {
            float l = smemok ? s_lab[j] : __ldg(labels + start + j);
            float s = smemok ? s_sc[j]  : __ldg(scores + start + j);
            float pt = __expf(l - mL) * invL;
            float pp = __expf(s - mS) * invS;
            item_sum += pt * __logf(pp + EPSV);
        }
    }

    // group reduce; discard invalid weeks (n < 2); NaNs from empty groups
    // are eliminated by the select below.
    item_sum = gsum(item_sum, gm);
    const bool valid = (nseg >= 2);
    float t = (sub == 0 && valid) ? item_sum : 0.0f;
    float c = (sub == 0 && valid) ? 1.0f     : 0.0f;

    // warp reduce (unconditional, full mask)
#pragma unroll
    for (int o = 16; o; o >>= 1) {
        t += __shfl_xor_sync(0xffffffffu, t, o);
        c += __shfl_xor_sync(0xffffffffu, c, o);
    }
    if ((tid & 31) == 0) { s_wt[tid >> 5] = t; s_wc[tid >> 5] = c; }
    __syncthreads();
    if (tid == 0) {
        float tt = 0.0f, cc = 0.0f;
#pragma unroll
        for (int k = 0; k < THREADS / 32; k++) { tt += s_wt[k]; cc += s_wc[k]; }
        g_part_tot[blockIdx.x] = tt;
        g_part_cnt[blockIdx.x] = cc;
    }
}

// ---------------------------------------------------------------------------
// finalize: reduce 4096 partials -> scalar loss
// ---------------------------------------------------------------------------
__global__ __launch_bounds__(1024)
void finalize_kernel(float* __restrict__ out) {
    float t = 0.0f, c = 0.0f;
    for (int i = threadIdx.x; i < GRID1; i += 1024) {
        t += g_part_tot[i];
        c += g_part_cnt[i];
    }
#pragma unroll
    for (int o = 16; o; o >>= 1) {
        t += __shfl_xor_sync(0xffffffffu, t, o);
        c += __shfl_xor_sync(0xffffffffu, c, o);
    }
    __shared__ float sh_t[32];
    __shared__ float sh_c[32];
    const int warp = threadIdx.x >> 5;
    const int lane = threadIdx.x & 31;
    if (lane == 0) { sh_t[warp] = t; sh_c[warp] = c; }
    __syncthreads();
    if (warp == 0) {
        t = sh_t[lane];
        c = sh_c[lane];
#pragma unroll
        for (int o = 16; o; o >>= 1) {
            t += __shfl_xor_sync(0xffffffffu, t, o);
            c += __shfl_xor_sync(0xffffffffu, c, o);
        }
        if (lane == 0)
            out[0] = (c > 0.0f) ? (-t / fmaxf(c, 1.0f)) : 0.0f;
    }
}

extern "C" void kernel_launch(void* const* d_in, const int* in_sizes, int n_in,
                              void* d_out, int out_size) {
    const float* scores = (const float*)d_in[0];
    const float* labels = (const float*)d_in[1];
    const int*   idx    = (const int*)d_in[2];
    const int n = in_sizes[0];

    listnet_kernel<<<GRID1, THREADS>>>(scores, labels, idx, n);
    finalize_kernel<<<1, 1024>>>((float*)d_out);
}